// round 4
// baseline (speedup 1.0000x reference)
#include <cuda_runtime.h>
#include <math.h>

#define BB 64
#define SS 48
#define EE 512
#define HH 512
#define GG 2048           // 4H
#define M0 (SS*BB)        // 3072

typedef unsigned long long ull;

// ---------------- scratch (device globals; no allocation allowed) ----------------
__device__ float d_xseq[M0*EE];                 // x permuted to [S*B][E]
__device__ float d_g0[2*M0*GG];                 // layer0 input gates (post-LN)  ~50MB
__device__ float d_raw0[2*BB*GG];               // K-split partial 0
__device__ float d_raw1[2*BB*GG];               // K-split partial 1
__device__ float d_h[2*BB*HH];
__device__ float d_c[2*BB*HH];
__device__ float d_xc[BB*2*HH];                 // concat(hf,hb) layer0 output
__device__ float d_g1[2*BB*GG];                 // layer1 input gates (post-LN)

// ---------------- f32x2 helpers (Blackwell packed fp32 FMA) ----------------
__device__ __forceinline__ ull pack2(float a){
    ull r; asm("mov.b64 %0, {%1, %1};" : "=l"(r) : "f"(a)); return r;
}
__device__ __forceinline__ ull fma2(ull a, ull b, ull c){
    ull d; asm("fma.rn.f32x2 %0, %1, %2, %3;" : "=l"(d) : "l"(a), "l"(b), "l"(c)); return d;
}

// ---------------- block reduction (256 threads = 8 warps) ----------------
__device__ __forceinline__ float2 blockReduce2(float s, float s2, float* red){
    #pragma unroll
    for(int o=16;o>0;o>>=1){
        s  += __shfl_down_sync(0xffffffffu, s,  o);
        s2 += __shfl_down_sync(0xffffffffu, s2, o);
    }
    int w = threadIdx.x >> 5, l = threadIdx.x & 31;
    __syncthreads();                 // protect red[] reuse
    if(l==0){ red[w] = s; red[w+8] = s2; }
    __syncthreads();
    float ts = red[0], ts2 = red[8];
    #pragma unroll
    for(int i=1;i<8;i++){ ts += red[i]; ts2 += red[i+8]; }
    return make_float2(ts, ts2);
}

// ---------------- small utility kernels ----------------
__global__ void zero_hc(){
    int i = blockIdx.x*blockDim.x + threadIdx.x;   // 32768 threads
    float4 z = make_float4(0.f,0.f,0.f,0.f);
    if(i < 16384)      ((float4*)d_h)[i] = z;
    else               ((float4*)d_c)[i-16384] = z;
}

__global__ void permute_x(const float* __restrict__ x){
    int i = blockIdx.x*blockDim.x + threadIdx.x;   // 393216 float4
    int e4 = i & 127;            // 128 float4 per 512-row
    int m  = i >> 7;             // 0..3071  (m = s*B + b)
    int s = m / BB, b = m % BB;
    float4 v = ((const float4*)x)[ (size_t)(b*SS + s)*128 + e4 ];
    ((float4*)d_xseq)[ (size_t)m*128 + e4 ] = v;
}

__global__ void copy_concat(int to_out, float* out){
    int b = blockIdx.x, tid = threadIdx.x;
    float* dst = to_out ? (out + (size_t)b*1024) : (d_xc + (size_t)b*1024);
    #pragma unroll
    for(int p=0;p<4;p++){
        int idx = tid + 256*p;    // 0..1023
        float v = (idx < HH) ? d_h[(size_t)b*HH + idx]
                             : d_h[(size_t)BB*HH + (size_t)b*HH + (idx-HH)];
        dst[idx] = v;
    }
}

// ---------------- big GEMM: layer0 input gates ----------------
// C[dir][m][n] = sum_k xseq[m][k] * Wih0[dir][n][k]
// tile 128x128x16, 256 threads, 8x8 microtile via f32x2
#define LDSA 132
__global__ __launch_bounds__(256,2) void gemm_ih0(const float* __restrict__ W){
    __shared__ float As[16*LDSA];
    __shared__ float Bs[16*LDSA];
    int dir = blockIdx.z, bm = blockIdx.y, bn = blockIdx.x;
    const float* Ab = d_xseq + (size_t)bm*128*EE;
    const float* Wb = W + ((size_t)dir*GG + bn*128)*EE;
    int tid = threadIdx.x;
    int lm = tid >> 2;            // 0..63
    int k4 = (tid & 3) * 4;       // 0,4,8,12
    int tm = tid >> 4, tn = tid & 15;
    ull acc[8][4];
    #pragma unroll
    for(int i=0;i<8;i++)
        #pragma unroll
        for(int j=0;j<4;j++) acc[i][j] = 0ull;

    for(int kt=0; kt<EE; kt+=16){
        float4 a0 = *(const float4*)(Ab + (size_t)lm*EE       + kt + k4);
        float4 a1 = *(const float4*)(Ab + (size_t)(lm+64)*EE  + kt + k4);
        float4 b0 = *(const float4*)(Wb + (size_t)lm*EE       + kt + k4);
        float4 b1 = *(const float4*)(Wb + (size_t)(lm+64)*EE  + kt + k4);
        __syncthreads();
        As[(k4+0)*LDSA+lm]    = a0.x; As[(k4+1)*LDSA+lm]    = a0.y;
        As[(k4+2)*LDSA+lm]    = a0.z; As[(k4+3)*LDSA+lm]    = a0.w;
        As[(k4+0)*LDSA+lm+64] = a1.x; As[(k4+1)*LDSA+lm+64] = a1.y;
        As[(k4+2)*LDSA+lm+64] = a1.z; As[(k4+3)*LDSA+lm+64] = a1.w;
        Bs[(k4+0)*LDSA+lm]    = b0.x; Bs[(k4+1)*LDSA+lm]    = b0.y;
        Bs[(k4+2)*LDSA+lm]    = b0.z; Bs[(k4+3)*LDSA+lm]    = b0.w;
        Bs[(k4+0)*LDSA+lm+64] = b1.x; Bs[(k4+1)*LDSA+lm+64] = b1.y;
        Bs[(k4+2)*LDSA+lm+64] = b1.z; Bs[(k4+3)*LDSA+lm+64] = b1.w;
        __syncthreads();
        #pragma unroll
        for(int k=0;k<16;k++){
            float4 af0 = *(const float4*)&As[k*LDSA + tm*8];
            float4 af1 = *(const float4*)&As[k*LDSA + tm*8 + 4];
            ulonglong2 bb0 = *(const ulonglong2*)&Bs[k*LDSA + tn*8];
            ulonglong2 bb1 = *(const ulonglong2*)&Bs[k*LDSA + tn*8 + 4];
            ull bfr[4] = {bb0.x, bb0.y, bb1.x, bb1.y};
            float afr[8] = {af0.x,af0.y,af0.z,af0.w,af1.x,af1.y,af1.z,af1.w};
            #pragma unroll
            for(int i=0;i<8;i++){
                ull aa = pack2(afr[i]);
                #pragma unroll
                for(int j=0;j<4;j++) acc[i][j] = fma2(aa, bfr[j], acc[i][j]);
            }
        }
    }
    float* C = d_g0 + ((size_t)dir*M0 + (size_t)bm*128)*GG + bn*128;
    #pragma unroll
    for(int i=0;i<8;i++){
        float* crow = C + (size_t)(tm*8+i)*GG + tn*8;
        union { ull u[2]; float4 f; } u0, u1;
        u0.u[0]=acc[i][0]; u0.u[1]=acc[i][1];
        u1.u[0]=acc[i][2]; u1.u[1]=acc[i][3];
        *(float4*)crow     = u0.f;
        *(float4*)(crow+4) = u1.f;
    }
}

// ---------------- small GEMM: recurrence + layer1 input ----------------
// out[ks][dir][b][gt*64+n] = sum_{k in K-half ks} A[b][k] * W[dir][gt*64+n][k]
// grid (32, 2, 2) = (gtile, ksplit, dir), 128 threads, 4x8 microtile
#define LDSS 68
__global__ __launch_bounds__(128) void step_gemm(int a_sel, const float* __restrict__ W, int Ktot){
    __shared__ float As[16*LDSS];
    __shared__ float Bs[16*LDSS];
    int gt = blockIdx.x, ks = blockIdx.y, dir = blockIdx.z;
    int Kc = Ktot >> 1;
    int k0 = ks * Kc;
    const float* Ab; int lda;
    if(a_sel){ Ab = d_xc;                         lda = 2*HH; }
    else     { Ab = d_h + (size_t)dir*BB*HH;      lda = HH;   }
    const float* Wb = W + ((size_t)dir*GG + gt*64)*Ktot;
    int tid = threadIdx.x;
    int lm = tid >> 2;            // 0..31
    int k4 = (tid & 3) * 4;
    int tm = tid >> 3, tn = tid & 7;
    ull acc[4][4];
    #pragma unroll
    for(int i=0;i<4;i++)
        #pragma unroll
        for(int j=0;j<4;j++) acc[i][j] = 0ull;

    for(int kt=0; kt<Kc; kt+=16){
        float4 a0 = *(const float4*)(Ab + (size_t)lm*lda      + k0 + kt + k4);
        float4 a1 = *(const float4*)(Ab + (size_t)(lm+32)*lda + k0 + kt + k4);
        float4 b0 = *(const float4*)(Wb + (size_t)lm*Ktot      + k0 + kt + k4);
        float4 b1 = *(const float4*)(Wb + (size_t)(lm+32)*Ktot + k0 + kt + k4);
        __syncthreads();
        As[(k4+0)*LDSS+lm]    = a0.x; As[(k4+1)*LDSS+lm]    = a0.y;
        As[(k4+2)*LDSS+lm]    = a0.z; As[(k4+3)*LDSS+lm]    = a0.w;
        As[(k4+0)*LDSS+lm+32] = a1.x; As[(k4+1)*LDSS+lm+32] = a1.y;
        As[(k4+2)*LDSS+lm+32] = a1.z; As[(k4+3)*LDSS+lm+32] = a1.w;
        Bs[(k4+0)*LDSS+lm]    = b0.x; Bs[(k4+1)*LDSS+lm]    = b0.y;
        Bs[(k4+2)*LDSS+lm]    = b0.z; Bs[(k4+3)*LDSS+lm]    = b0.w;
        Bs[(k4+0)*LDSS+lm+32] = b1.x; Bs[(k4+1)*LDSS+lm+32] = b1.y;
        Bs[(k4+2)*LDSS+lm+32] = b1.z; Bs[(k4+3)*LDSS+lm+32] = b1.w;
        __syncthreads();
        #pragma unroll
        for(int k=0;k<16;k++){
            float4 af = *(const float4*)&As[k*LDSS + tm*4];
            ulonglong2 bb0 = *(const ulonglong2*)&Bs[k*LDSS + tn*8];
            ulonglong2 bb1 = *(const ulonglong2*)&Bs[k*LDSS + tn*8 + 4];
            ull bfr[4] = {bb0.x, bb0.y, bb1.x, bb1.y};
            float afr[4] = {af.x, af.y, af.z, af.w};
            #pragma unroll
            for(int i=0;i<4;i++){
                ull aa = pack2(afr[i]);
                #pragma unroll
                for(int j=0;j<4;j++) acc[i][j] = fma2(aa, bfr[j], acc[i][j]);
            }
        }
    }
    float* Ob = (ks ? d_raw1 : d_raw0) + (size_t)dir*BB*GG + gt*64;
    #pragma unroll
    for(int i=0;i<4;i++){
        float* crow = Ob + (size_t)(tm*4+i)*GG + tn*8;
        union { ull u[2]; float4 f; } u0, u1;
        u0.u[0]=acc[i][0]; u0.u[1]=acc[i][1];
        u1.u[0]=acc[i][2]; u1.u[1]=acc[i][3];
        *(float4*)crow     = u0.f;
        *(float4*)(crow+4) = u1.f;
    }
}

// ---------------- row LayerNorm (width 2048) ----------------
// mode 0: in-place on d_g0 (rows_per_dir = 3072), gamma/beta = ln_ih0
// mode 1: d_g1 = LN(d_raw0 + d_raw1)   (rows_per_dir = 64), gamma/beta = ln_ih1
__global__ __launch_bounds__(256) void ln_rows(int mode, const float* __restrict__ gam,
                                               const float* __restrict__ bet, int rows_per_dir){
    __shared__ float red[16];
    int row = blockIdx.x, tid = threadIdx.x;
    int dir = row / rows_per_dir;
    const float *s0, *s1 = nullptr; float* dst;
    if(mode==0){ dst = d_g0 + (size_t)row*GG; s0 = dst; }
    else       { s0 = d_raw0 + (size_t)row*GG; s1 = d_raw1 + (size_t)row*GG; dst = d_g1 + (size_t)row*GG; }
    float v[8]; float s=0.f, s2=0.f;
    #pragma unroll
    for(int r=0;r<8;r++){
        int j = tid + 256*r;
        float x = s0[j];
        if(mode) x += s1[j];
        v[r] = x; s += x; s2 += x*x;
    }
    float2 tt = blockReduce2(s, s2, red);
    float mu   = tt.x * (1.f/GG);
    float var  = tt.y * (1.f/GG) - mu*mu;
    float rstd = rsqrtf(var + 1e-5f);
    #pragma unroll
    for(int r=0;r<8;r++){
        int j = tid + 256*r;
        dst[j] = (v[r]-mu)*rstd*gam[dir*GG+j] + bet[dir*GG+j];
    }
}

// ---------------- fused LSTM pointwise step ----------------
// one CTA per (dir, b): LN(h@Whh) + gih, activations, c update, LN(c), h out
__global__ __launch_bounds__(256) void pointwise(int layer, int t,
        const float* __restrict__ lnhh_g, const float* __restrict__ lnhh_b,
        const float* __restrict__ lnho_g, const float* __restrict__ lnho_b){
    __shared__ float smg[GG];
    __shared__ float red[16];
    int b = blockIdx.x, dir = blockIdx.y, tid = threadIdx.x;
    const float* gih;
    if(layer==0){
        int s = dir ? (SS-1-t) : t;
        gih = d_g0 + ((size_t)dir*M0 + (size_t)s*BB + b)*GG;
    } else {
        gih = d_g1 + ((size_t)dir*BB + b)*GG;
    }
    const float* r0 = d_raw0 + ((size_t)dir*BB + b)*GG;
    const float* r1 = d_raw1 + ((size_t)dir*BB + b)*GG;

    float raw[8]; float s=0.f, s2=0.f;
    #pragma unroll
    for(int r=0;r<8;r++){
        int j = tid + 256*r;
        float v = r0[j] + r1[j];
        raw[r] = v; s += v; s2 += v*v;
    }
    float2 tt = blockReduce2(s, s2, red);
    float mu   = tt.x * (1.f/GG);
    float var  = tt.y * (1.f/GG) - mu*mu;
    float rstd = rsqrtf(var + 1e-5f);
    #pragma unroll
    for(int r=0;r<8;r++){
        int j = tid + 256*r;
        float gate = gih[j] + (raw[r]-mu)*rstd*lnhh_g[dir*GG+j] + lnhh_b[dir*GG+j];
        smg[j] = (j < 3*HH) ? (1.f/(1.f+expf(-gate))) : tanhf(gate);
    }
    __syncthreads();

    float* cp = d_c + ((size_t)dir*BB + b)*HH;
    float* hp = d_h + ((size_t)dir*BB + b)*HH;
    float cn[2], ov[2]; float cs=0.f, cs2=0.f;
    #pragma unroll
    for(int r=0;r<2;r++){
        int idx = tid + 256*r;
        float i_ = smg[idx];
        float f_ = smg[HH   + idx];
        float o_ = smg[2*HH + idx];
        float g_ = smg[3*HH + idx];
        float c2 = f_*cp[idx] + i_*g_;
        cp[idx] = c2; cn[r] = c2; ov[r] = o_;
        cs += c2; cs2 += c2*c2;
    }
    float2 t2 = blockReduce2(cs, cs2, red);
    float mu2   = t2.x * (1.f/HH);
    float var2  = t2.y * (1.f/HH) - mu2*mu2;
    float rstd2 = rsqrtf(var2 + 1e-5f);
    #pragma unroll
    for(int r=0;r<2;r++){
        int idx = tid + 256*r;
        float lnc = (cn[r]-mu2)*rstd2*lnho_g[dir*HH+idx] + lnho_b[dir*HH+idx];
        hp[idx] = ov[r]*tanhf(lnc);
    }
}

// ---------------- launch ----------------
extern "C" void kernel_launch(void* const* d_in, const int* in_sizes, int n_in,
                              void* d_out, int out_size){
    const float* x        = (const float*)d_in[0];
    // d_in[1] = text_length (unused)
    const float* w_ih0    = (const float*)d_in[2];
    const float* w_hh0    = (const float*)d_in[3];
    const float* ln_ih0_g = (const float*)d_in[4];
    const float* ln_ih0_b = (const float*)d_in[5];
    const float* ln_hh0_g = (const float*)d_in[6];
    const float* ln_hh0_b = (const float*)d_in[7];
    const float* ln_ho0_g = (const float*)d_in[8];
    const float* ln_ho0_b = (const float*)d_in[9];
    const float* w_ih1    = (const float*)d_in[10];
    const float* w_hh1    = (const float*)d_in[11];
    const float* ln_ih1_g = (const float*)d_in[12];
    const float* ln_ih1_b = (const float*)d_in[13];
    const float* ln_hh1_g = (const float*)d_in[14];
    const float* ln_hh1_b = (const float*)d_in[15];
    const float* ln_ho1_g = (const float*)d_in[16];
    const float* ln_ho1_b = (const float*)d_in[17];
    float* out = (float*)d_out;

    // phase 0: init + layer0 input gates
    zero_hc<<<128,256>>>();
    permute_x<<<1536,256>>>(x);
    gemm_ih0<<<dim3(16,24,2),256>>>(w_ih0);
    ln_rows<<<2*M0,256>>>(0, ln_ih0_g, ln_ih0_b, M0);

    // phase 1: layer0 recurrence (fwd+bwd in parallel per round)
    for(int t=0; t<SS; t++){
        step_gemm<<<dim3(32,2,2),128>>>(0, w_hh0, HH);
        pointwise<<<dim3(BB,2),256>>>(0, t, ln_hh0_g, ln_hh0_b, ln_ho0_g, ln_ho0_b);
    }

    // phase 2: layer1 input gates (computed once — aliasing bug makes input constant)
    copy_concat<<<BB,256>>>(0, nullptr);
    zero_hc<<<128,256>>>();
    step_gemm<<<dim3(32,2,2),128>>>(1, w_ih1, 2*HH);
    ln_rows<<<2*BB,256>>>(1, ln_ih1_g, ln_ih1_b, BB);

    // phase 3: layer1 recurrence (reverse over constant input == forward)
    for(int t=0; t<SS; t++){
        step_gemm<<<dim3(32,2,2),128>>>(0, w_hh1, HH);
        pointwise<<<dim3(BB,2),256>>>(1, t, ln_hh1_g, ln_hh1_b, ln_ho1_g, ln_ho1_b);
    }

    // phase 4: output = concat(hf1, hb1)
    copy_concat<<<BB,256>>>(1, out);
}